// round 15
// baseline (speedup 1.0000x reference)
#include <cuda_runtime.h>
#include <cuda_fp16.h>

#define N_NODES 100000
#define N_EDGES 1600000
#define IN_F 128
#define H_F 64
#define OUT_F 32
#define SCAN_BLK 1024
#define NB_SCAN ((N_NODES + SCAN_BLK - 1) / SCAN_BLK)   // 98

// ---------------- scratch (device globals: no allocation allowed) ----------
__device__ int    d_cnt      [N_NODES + 32];       // zero at entry (invariant)
__device__ float  d_dinv     [N_NODES];
__device__ int    d_rowptr   [N_NODES + 1];
__device__ int    d_bsum     [128];
__device__ int    d_rank     [N_EDGES];            // edge rank within dst row
__device__ int    d_srcsorted[N_EDGES];            // CSR-by-dst src list (6.4MB)
__device__ __half d_g1       [N_NODES * H_F];      // UNSCALED L1 transform (fp16)
__device__ float  d_h1       [N_NODES * H_F];      // relu(dinv*agg + b1)
__device__ __half d_g2       [N_NODES * OUT_F];    // dinv-scaled L2 transform

// ---------------- packed fp32x2 helpers (FFMA2) ------------------------------
__device__ __forceinline__ unsigned long long dup_f32(float x) {
    unsigned long long r;
    asm("mov.b64 %0, {%1, %1};" : "=l"(r) : "f"(x));
    return r;
}
__device__ __forceinline__ void fma2(unsigned long long& d,
                                     unsigned long long a,
                                     unsigned long long b) {
    asm("fma.rn.f32x2 %0, %1, %2, %3;" : "=l"(d) : "l"(a), "l"(b), "l"(d));
}
__device__ __forceinline__ float2 unpack_f32x2(unsigned long long v) {
    float2 f;
    asm("mov.b64 {%0, %1}, %2;" : "=f"(f.x), "=f"(f.y) : "l"(v));
    return f;
}

// ---------------- count + RANK: p = atomicAdd is the edge's rank ------------
// Persisting the atomic's return makes the later fill atomic-free.
// Requires d_cnt == 0 at entry: true initially and re-set by scan_c.
__global__ void count_rank_kernel(const int* __restrict__ ei) {
    int t = blockIdx.x * blockDim.x + threadIdx.x;
    if (t < N_EDGES / 4) {
        int4 d = reinterpret_cast<const int4*>(ei + N_EDGES)[t];
        int4 r;
        r.x = atomicAdd(&d_cnt[d.x], 1);
        r.y = atomicAdd(&d_cnt[d.y], 1);
        r.z = atomicAdd(&d_cnt[d.z], 1);
        r.w = atomicAdd(&d_cnt[d.w], 1);
        reinterpret_cast<int4*>(d_rank)[t] = r;     // coalesced
    }
}

// ---------------- scan A: block-local exclusive scan + block sums -----------
__global__ void scan_a_kernel() {
    __shared__ int wpre[32];
    const int tid  = threadIdx.x;
    const int lane = tid & 31;
    const int wid  = tid >> 5;
    const int gid  = blockIdx.x * SCAN_BLK + tid;
    int v = (gid < N_NODES) ? d_cnt[gid] : 0;

    int inc = v;
    #pragma unroll
    for (int o = 1; o < 32; o <<= 1) {
        int t = __shfl_up_sync(0xffffffffu, inc, o);
        if (lane >= o) inc += t;
    }
    if (lane == 31) wpre[wid] = inc;
    __syncthreads();
    if (wid == 0) {
        int s = wpre[lane];
        #pragma unroll
        for (int o = 1; o < 32; o <<= 1) {
            int t = __shfl_up_sync(0xffffffffu, s, o);
            if (lane >= o) s += t;
        }
        wpre[lane] = s;                       // inclusive warp-sum scan
    }
    __syncthreads();
    int base = (wid > 0) ? wpre[wid - 1] : 0;
    if (gid < N_NODES) d_rowptr[gid] = base + inc - v;   // block-local exclusive
    if (tid == SCAN_BLK - 1) d_bsum[blockIdx.x] = wpre[31];   // raw block total
}

// ---------------- scan C: globalize + dinv + cnt re-zero ---------------------
__global__ void scan_c_kernel() {
    __shared__ int base;
    const int tid = threadIdx.x;
    const int gid = blockIdx.x * 256 + tid;
    const int chunk = blockIdx.x >> 2;      // # scan_a blocks before this range
    if (tid == 0) base = 0;
    __syncthreads();
    if (tid < chunk) atomicAdd(&base, d_bsum[tid]);
    __syncthreads();
    if (gid < N_NODES) {
        d_rowptr[gid] += base;
        d_dinv[gid] = rsqrtf((float)(d_cnt[gid] + 1));   // +1 self loop
        d_cnt[gid] = 0;                      // re-zero for next replay
    }
    if (gid == 0) d_rowptr[N_NODES] = N_EDGES;
}

// ---------------- CSR fill: ATOMIC-FREE via precomputed ranks ---------------
// pos = rowptr[dst] + rank[edge]; pure loads + fire-and-forget stores.
__global__ void fill_kernel(const int* __restrict__ ei) {
    int t = blockIdx.x * blockDim.x + threadIdx.x;
    if (t < N_EDGES / 4) {
        int4 s = reinterpret_cast<const int4*>(ei)[t];
        int4 d = reinterpret_cast<const int4*>(ei + N_EDGES)[t];
        int4 r = reinterpret_cast<const int4*>(d_rank)[t];
        d_srcsorted[__ldg(&d_rowptr[d.x]) + r.x] = s.x;
        d_srcsorted[__ldg(&d_rowptr[d.y]) + r.y] = s.y;
        d_srcsorted[__ldg(&d_rowptr[d.z]) + r.z] = s.z;
        d_srcsorted[__ldg(&d_rowptr[d.w]) + r.w] = s.w;
    }
}

// ---------------- GEMM1: g1[i,c] = fp16( x[i,:] . W1[c,:] ) — NO dinv -------
__global__ void gemm1_kernel(const float* __restrict__ x,
                             const float* __restrict__ W1) {
    __shared__ float xs[128 * 68];   // xs[k][r]
    __shared__ float Wt[32 * 68];    // Wt[kl][c]
    const int tid = threadIdx.x;
    const int row0 = blockIdx.x * 64;

    for (int idx = tid; idx < 64 * 128; idx += 256) {
        int r = idx >> 7, k = idx & 127;
        int row = row0 + r;
        xs[k * 68 + r] = (row < N_NODES) ? x[row * IN_F + k] : 0.f;
    }

    const int r0 = (tid >> 4) * 4;
    const int c0 = (tid & 15) * 4;
    unsigned long long acc2[4][2] = {};   // [row][colpair]

    for (int kc = 0; kc < 4; ++kc) {
        __syncthreads();
        for (int idx = tid; idx < 64 * 32; idx += 256) {
            int c = idx >> 5, kl = idx & 31;
            Wt[kl * 68 + c] = W1[c * IN_F + kc * 32 + kl];
        }
        __syncthreads();
        #pragma unroll
        for (int kl = 0; kl < 32; ++kl) {
            int k = kc * 32 + kl;
            float4 xv = *reinterpret_cast<const float4*>(&xs[k * 68 + r0]);
            const unsigned long long* wp =
                reinterpret_cast<const unsigned long long*>(&Wt[kl * 68 + c0]);
            unsigned long long w0 = wp[0];
            unsigned long long w1 = wp[1];
            unsigned long long x0 = dup_f32(xv.x);
            unsigned long long x1 = dup_f32(xv.y);
            unsigned long long x2 = dup_f32(xv.z);
            unsigned long long x3 = dup_f32(xv.w);
            fma2(acc2[0][0], x0, w0); fma2(acc2[0][1], x0, w1);
            fma2(acc2[1][0], x1, w0); fma2(acc2[1][1], x1, w1);
            fma2(acc2[2][0], x2, w0); fma2(acc2[2][1], x2, w1);
            fma2(acc2[3][0], x3, w0); fma2(acc2[3][1], x3, w1);
        }
    }

    #pragma unroll
    for (int i = 0; i < 4; ++i) {
        int row = row0 + r0 + i;
        if (row < N_NODES) {
            float2 a = unpack_f32x2(acc2[i][0]);
            float2 b = unpack_f32x2(acc2[i][1]);
            __half2 p0 = __floats2half2_rn(a.x, a.y);
            __half2 p1 = __floats2half2_rn(b.x, b.y);
            __half2* dst = reinterpret_cast<__half2*>(&d_g1[row * H_F + c0]);
            dst[0] = p0;
            dst[1] = p1;
        }
    }
}

// ---------------- gather L1: h = relu(dinv[i]*(Σ dinv[s]*g1[s]) + b1) -------
// One warp per dst node; fully masked 8-wide groups (no serial remainder).
__global__ void gather1_kernel(const float* __restrict__ b1) {
    int warp = (blockIdx.x * blockDim.x + threadIdx.x) >> 5;
    int lane = threadIdx.x & 31;
    if (warp >= N_NODES) return;

    const __half2* g = reinterpret_cast<const __half2*>(d_g1);
    const int* __restrict__ ss = d_srcsorted;
    const float* __restrict__ dv = d_dinv;

    const float di = dv[warp];
    float2 sv = __half22float2(g[warp * 32 + lane]);
    float2 acc;                                      // self loop: dinv[i]*g1[i]
    acc.x = di * sv.x;
    acc.y = di * sv.y;
    int e = d_rowptr[warp];
    const int end = d_rowptr[warp + 1];

    for (; e < end; e += 8) {
        const int last = end - 1;
        int i0 = e + 0 < end ? e + 0 : last;
        int i1 = e + 1 < end ? e + 1 : last;
        int i2 = e + 2 < end ? e + 2 : last;
        int i3 = e + 3 < end ? e + 3 : last;
        int i4 = e + 4 < end ? e + 4 : last;
        int i5 = e + 5 < end ? e + 5 : last;
        int i6 = e + 6 < end ? e + 6 : last;
        int i7 = e + 7 < end ? e + 7 : last;
        int s0 = __ldg(&ss[i0]);
        int s1 = __ldg(&ss[i1]);
        int s2 = __ldg(&ss[i2]);
        int s3 = __ldg(&ss[i3]);
        int s4 = __ldg(&ss[i4]);
        int s5 = __ldg(&ss[i5]);
        int s6 = __ldg(&ss[i6]);
        int s7 = __ldg(&ss[i7]);
        float e0 =                 __ldg(&dv[s0]);          // e+0 < end always
        float e1 = e + 1 < end ? __ldg(&dv[s1]) : 0.f;
        float e2 = e + 2 < end ? __ldg(&dv[s2]) : 0.f;
        float e3 = e + 3 < end ? __ldg(&dv[s3]) : 0.f;
        float e4 = e + 4 < end ? __ldg(&dv[s4]) : 0.f;
        float e5 = e + 5 < end ? __ldg(&dv[s5]) : 0.f;
        float e6 = e + 6 < end ? __ldg(&dv[s6]) : 0.f;
        float e7 = e + 7 < end ? __ldg(&dv[s7]) : 0.f;
        float2 v0 = __half22float2(__ldg(&g[s0 * 32 + lane]));
        float2 v1 = __half22float2(__ldg(&g[s1 * 32 + lane]));
        float2 v2 = __half22float2(__ldg(&g[s2 * 32 + lane]));
        float2 v3 = __half22float2(__ldg(&g[s3 * 32 + lane]));
        float2 v4 = __half22float2(__ldg(&g[s4 * 32 + lane]));
        float2 v5 = __half22float2(__ldg(&g[s5 * 32 + lane]));
        float2 v6 = __half22float2(__ldg(&g[s6 * 32 + lane]));
        float2 v7 = __half22float2(__ldg(&g[s7 * 32 + lane]));
        float px, py, qx, qy;
        px = fmaf(e0, v0.x, fmaf(e1, v1.x, fmaf(e2, v2.x, e3 * v3.x)));
        py = fmaf(e0, v0.y, fmaf(e1, v1.y, fmaf(e2, v2.y, e3 * v3.y)));
        qx = fmaf(e4, v4.x, fmaf(e5, v5.x, fmaf(e6, v6.x, e7 * v7.x)));
        qy = fmaf(e4, v4.y, fmaf(e5, v5.y, fmaf(e6, v6.y, e7 * v7.y)));
        acc.x += px + qx;
        acc.y += py + qy;
    }

    float2 b = __ldg(reinterpret_cast<const float2*>(b1) + lane);
    float2 h;
    h.x = fmaxf(fmaf(di, acc.x, b.x), 0.f);
    h.y = fmaxf(fmaf(di, acc.y, b.y), 0.f);
    reinterpret_cast<float2*>(d_h1)[warp * 32 + lane] = h;
}

// ---------------- GEMM2: g2[i,c] = fp16( dinv[i] * (h1[i,:] . W2[c,:]) ) -----
__global__ void gemm2_kernel(const float* __restrict__ W2) {
    __shared__ float ht[64 * 66];    // ht[j][r]
    __shared__ float Wt[64 * 36];    // Wt[j][c]
    const int tid = threadIdx.x;
    const int row0 = blockIdx.x * 64;

    for (int idx = tid; idx < 64 * 64; idx += 256) {
        int r = idx >> 6, j = idx & 63;
        int row = row0 + r;
        ht[j * 66 + r] = (row < N_NODES) ? d_h1[row * H_F + j] : 0.f;
    }
    for (int idx = tid; idx < 32 * 64; idx += 256) {
        int c = idx >> 6, j = idx & 63;
        Wt[j * 36 + c] = W2[c * H_F + j];
    }
    __syncthreads();

    const int r0 = (tid >> 3) * 2;
    const int c0 = (tid & 7) * 4;
    unsigned long long acc2[2][2] = {};

    #pragma unroll
    for (int j = 0; j < 64; ++j) {
        float2 hv = *reinterpret_cast<const float2*>(&ht[j * 66 + r0]);
        const unsigned long long* wp =
            reinterpret_cast<const unsigned long long*>(&Wt[j * 36 + c0]);
        unsigned long long w0 = wp[0];
        unsigned long long w1 = wp[1];
        unsigned long long h0 = dup_f32(hv.x);
        unsigned long long h1 = dup_f32(hv.y);
        fma2(acc2[0][0], h0, w0); fma2(acc2[0][1], h0, w1);
        fma2(acc2[1][0], h1, w0); fma2(acc2[1][1], h1, w1);
    }

    #pragma unroll
    for (int i = 0; i < 2; ++i) {
        int row = row0 + r0 + i;
        if (row < N_NODES) {
            float di = d_dinv[row];
            float2 a = unpack_f32x2(acc2[i][0]);
            float2 b = unpack_f32x2(acc2[i][1]);
            __half2 p0 = __floats2half2_rn(a.x * di, a.y * di);
            __half2 p1 = __floats2half2_rn(b.x * di, b.y * di);
            __half2* dst = reinterpret_cast<__half2*>(&d_g2[row * OUT_F + c0]);
            dst[0] = p0;
            dst[1] = p1;
        }
    }
}

// ---------------- gather L2: masked 8-wide; + bias -> output -----------------
__global__ void gather2_kernel(const float* __restrict__ b2,
                               float* __restrict__ out) {
    int warp = (blockIdx.x * blockDim.x + threadIdx.x) >> 5;
    int lane = threadIdx.x & 31;
    if (warp >= N_NODES) return;

    const int* __restrict__ ss = d_srcsorted;
    float acc = __half2float(d_g2[warp * OUT_F + lane]);   // self loop
    int e = d_rowptr[warp];
    const int end = d_rowptr[warp + 1];

    for (; e < end; e += 8) {
        const int last = end - 1;
        int i0 = e + 0 < end ? e + 0 : last;
        int i1 = e + 1 < end ? e + 1 : last;
        int i2 = e + 2 < end ? e + 2 : last;
        int i3 = e + 3 < end ? e + 3 : last;
        int i4 = e + 4 < end ? e + 4 : last;
        int i5 = e + 5 < end ? e + 5 : last;
        int i6 = e + 6 < end ? e + 6 : last;
        int i7 = e + 7 < end ? e + 7 : last;
        int s0 = __ldg(&ss[i0]);
        int s1 = __ldg(&ss[i1]);
        int s2 = __ldg(&ss[i2]);
        int s3 = __ldg(&ss[i3]);
        int s4 = __ldg(&ss[i4]);
        int s5 = __ldg(&ss[i5]);
        int s6 = __ldg(&ss[i6]);
        int s7 = __ldg(&ss[i7]);
        float v0 =                 __half2float(__ldg(&d_g2[s0 * OUT_F + lane]));
        float v1 = e + 1 < end ? __half2float(__ldg(&d_g2[s1 * OUT_F + lane])) : 0.f;
        float v2 = e + 2 < end ? __half2float(__ldg(&d_g2[s2 * OUT_F + lane])) : 0.f;
        float v3 = e + 3 < end ? __half2float(__ldg(&d_g2[s3 * OUT_F + lane])) : 0.f;
        float v4 = e + 4 < end ? __half2float(__ldg(&d_g2[s4 * OUT_F + lane])) : 0.f;
        float v5 = e + 5 < end ? __half2float(__ldg(&d_g2[s5 * OUT_F + lane])) : 0.f;
        float v6 = e + 6 < end ? __half2float(__ldg(&d_g2[s6 * OUT_F + lane])) : 0.f;
        float v7 = e + 7 < end ? __half2float(__ldg(&d_g2[s7 * OUT_F + lane])) : 0.f;
        acc += ((v0 + v1) + (v2 + v3)) + ((v4 + v5) + (v6 + v7));
    }

    out[warp * OUT_F + lane] = fmaf(d_dinv[warp], acc, __ldg(&b2[lane]));
}

extern "C" void kernel_launch(void* const* d_in, const int* in_sizes, int n_in,
                              void* d_out, int out_size) {
    const float* x  = (const float*)d_in[0];
    const int*   ei = (const int*)  d_in[1];
    const float* W1 = (const float*)d_in[2];
    const float* b1 = (const float*)d_in[3];
    const float* W2 = (const float*)d_in[4];
    const float* b2 = (const float*)d_in[5];
    float* out = (float*)d_out;

    // Fork: CSR build on side stream; gemm1 (FMA-bound) on the main stream.
    cudaStream_t s;
    cudaStreamCreateWithFlags(&s, cudaStreamNonBlocking);
    cudaEvent_t ev_fork, ev_join;
    cudaEventCreateWithFlags(&ev_fork, cudaEventDisableTiming);
    cudaEventCreateWithFlags(&ev_join, cudaEventDisableTiming);

    cudaEventRecord(ev_fork, 0);
    cudaStreamWaitEvent(s, ev_fork, 0);

    // side stream: rank-splitting CSR build (fill is atomic-free)
    count_rank_kernel<<<(N_EDGES / 4 + 255) / 256, 256, 0, s>>>(ei);
    scan_a_kernel    <<<NB_SCAN, SCAN_BLK, 0, s>>>();
    scan_c_kernel    <<<(N_NODES + 255) / 256, 256, 0, s>>>();
    fill_kernel      <<<(N_EDGES / 4 + 255) / 256, 256, 0, s>>>(ei);
    cudaEventRecord(ev_join, s);

    // main stream: gemm1 (independent of CSR/dinv)
    gemm1_kernel <<<(N_NODES + 63) / 64, 256>>>(x, W1);

    // join, then the dependent tail
    cudaStreamWaitEvent(0, ev_join, 0);
    gather1_kernel<<<(N_NODES * 32 + 255) / 256, 256>>>(b1);
    gemm2_kernel  <<<(N_NODES + 63) / 64, 256>>>(W2);
    gather2_kernel<<<(N_NODES * 32 + 255) / 256, 256>>>(b2, out);
    // NOTE: stream/event handles intentionally not destroyed — destroying
    // capture-participating handles mid-capture is hazardous; kernel_launch
    // is invoked only a handful of times, so the leak is bounded, host-side.
}

// round 16
// speedup vs baseline: 1.1444x; 1.1444x over previous
#include <cuda_runtime.h>
#include <cuda_fp16.h>

#define N_NODES 100000
#define N_EDGES 1600000
#define IN_F 128
#define H_F 64
#define OUT_F 32
#define SCAN_BLK 1024
#define NB_SCAN ((N_NODES + SCAN_BLK - 1) / SCAN_BLK)   // 98

// ---------------- scratch (device globals: no allocation allowed) ----------
__device__ int    d_cnt      [N_NODES + 32];       // zero at entry (invariant)
__device__ float  d_dinv     [N_NODES];
__device__ int    d_rowptr   [N_NODES + 1];
__device__ int    d_bsum     [128];
__device__ int    d_rank     [N_EDGES];            // edge rank within dst row
__device__ int    d_srcsorted[N_EDGES];            // CSR-by-dst src list (6.4MB)
__device__ __half d_g1       [N_NODES * H_F];      // UNSCALED L1 transform (fp16)
__device__ float  d_h1       [N_NODES * H_F];      // relu(dinv*agg + b1)
__device__ __half d_g2       [N_NODES * OUT_F];    // dinv-scaled L2 transform

// ---------------- packed fp32x2 helpers (FFMA2) ------------------------------
__device__ __forceinline__ unsigned long long dup_f32(float x) {
    unsigned long long r;
    asm("mov.b64 %0, {%1, %1};" : "=l"(r) : "f"(x));
    return r;
}
__device__ __forceinline__ void fma2(unsigned long long& d,
                                     unsigned long long a,
                                     unsigned long long b) {
    asm("fma.rn.f32x2 %0, %1, %2, %3;" : "=l"(d) : "l"(a), "l"(b), "l"(d));
}
__device__ __forceinline__ float2 unpack_f32x2(unsigned long long v) {
    float2 f;
    asm("mov.b64 {%0, %1}, %2;" : "=f"(f.x), "=f"(f.y) : "l"(v));
    return f;
}

// ---------------- count + RANK: 8 edges / thread (high MLP, few warps) ------
// The atomic's return value IS the edge's rank within its dst row; persisting
// it (coalesced int4 stores) makes the later fill atomic-free.
// Requires d_cnt == 0 at entry: true initially and re-set by scan_c.
__global__ void count_rank_kernel(const int* __restrict__ ei) {
    int t = blockIdx.x * blockDim.x + threadIdx.x;
    if (t < N_EDGES / 8) {
        const int4* dp = reinterpret_cast<const int4*>(ei + N_EDGES);
        int4 a = dp[t * 2 + 0];
        int4 b = dp[t * 2 + 1];
        int4 ra, rb;
        ra.x = atomicAdd(&d_cnt[a.x], 1);
        ra.y = atomicAdd(&d_cnt[a.y], 1);
        ra.z = atomicAdd(&d_cnt[a.z], 1);
        ra.w = atomicAdd(&d_cnt[a.w], 1);
        rb.x = atomicAdd(&d_cnt[b.x], 1);
        rb.y = atomicAdd(&d_cnt[b.y], 1);
        rb.z = atomicAdd(&d_cnt[b.z], 1);
        rb.w = atomicAdd(&d_cnt[b.w], 1);
        int4* rp = reinterpret_cast<int4*>(d_rank);
        rp[t * 2 + 0] = ra;                          // coalesced
        rp[t * 2 + 1] = rb;
    }
}

// ---------------- scan A: block-local exclusive scan + block sums -----------
__global__ void scan_a_kernel() {
    __shared__ int wpre[32];
    const int tid  = threadIdx.x;
    const int lane = tid & 31;
    const int wid  = tid >> 5;
    const int gid  = blockIdx.x * SCAN_BLK + tid;
    int v = (gid < N_NODES) ? d_cnt[gid] : 0;

    int inc = v;
    #pragma unroll
    for (int o = 1; o < 32; o <<= 1) {
        int t = __shfl_up_sync(0xffffffffu, inc, o);
        if (lane >= o) inc += t;
    }
    if (lane == 31) wpre[wid] = inc;
    __syncthreads();
    if (wid == 0) {
        int s = wpre[lane];
        #pragma unroll
        for (int o = 1; o < 32; o <<= 1) {
            int t = __shfl_up_sync(0xffffffffu, s, o);
            if (lane >= o) s += t;
        }
        wpre[lane] = s;                       // inclusive warp-sum scan
    }
    __syncthreads();
    int base = (wid > 0) ? wpre[wid - 1] : 0;
    if (gid < N_NODES) d_rowptr[gid] = base + inc - v;   // block-local exclusive
    if (tid == SCAN_BLK - 1) d_bsum[blockIdx.x] = wpre[31];   // raw block total
}

// ---------------- scan C: globalize + dinv + cnt re-zero ---------------------
__global__ void scan_c_kernel() {
    __shared__ int base;
    const int tid = threadIdx.x;
    const int gid = blockIdx.x * 256 + tid;
    const int chunk = blockIdx.x >> 2;      // # scan_a blocks before this range
    if (tid == 0) base = 0;
    __syncthreads();
    if (tid < chunk) atomicAdd(&base, d_bsum[tid]);
    __syncthreads();
    if (gid < N_NODES) {
        d_rowptr[gid] += base;
        d_dinv[gid] = rsqrtf((float)(d_cnt[gid] + 1));   // +1 self loop
        d_cnt[gid] = 0;                      // re-zero for next replay
    }
    if (gid == 0) d_rowptr[N_NODES] = N_EDGES;
}

// ---------------- CSR fill: ATOMIC-FREE via precomputed ranks ---------------
// pos = rowptr[dst] + rank[edge]; pure loads + fire-and-forget stores.
__global__ void fill_kernel(const int* __restrict__ ei) {
    int t = blockIdx.x * blockDim.x + threadIdx.x;
    if (t < N_EDGES / 4) {
        int4 s = reinterpret_cast<const int4*>(ei)[t];
        int4 d = reinterpret_cast<const int4*>(ei + N_EDGES)[t];
        int4 r = reinterpret_cast<const int4*>(d_rank)[t];
        d_srcsorted[__ldg(&d_rowptr[d.x]) + r.x] = s.x;
        d_srcsorted[__ldg(&d_rowptr[d.y]) + r.y] = s.y;
        d_srcsorted[__ldg(&d_rowptr[d.z]) + r.z] = s.z;
        d_srcsorted[__ldg(&d_rowptr[d.w]) + r.w] = s.w;
    }
}

// ---------------- GEMM1: g1[i,c] = fp16( x[i,:] . W1[c,:] ) — NO dinv -------
__global__ void gemm1_kernel(const float* __restrict__ x,
                             const float* __restrict__ W1) {
    __shared__ float xs[128 * 68];   // xs[k][r]
    __shared__ float Wt[32 * 68];    // Wt[kl][c]
    const int tid = threadIdx.x;
    const int row0 = blockIdx.x * 64;

    for (int idx = tid; idx < 64 * 128; idx += 256) {
        int r = idx >> 7, k = idx & 127;
        int row = row0 + r;
        xs[k * 68 + r] = (row < N_NODES) ? x[row * IN_F + k] : 0.f;
    }

    const int r0 = (tid >> 4) * 4;
    const int c0 = (tid & 15) * 4;
    unsigned long long acc2[4][2] = {};   // [row][colpair]

    for (int kc = 0; kc < 4; ++kc) {
        __syncthreads();
        for (int idx = tid; idx < 64 * 32; idx += 256) {
            int c = idx >> 5, kl = idx & 31;
            Wt[kl * 68 + c] = W1[c * IN_F + kc * 32 + kl];
        }
        __syncthreads();
        #pragma unroll
        for (int kl = 0; kl < 32; ++kl) {
            int k = kc * 32 + kl;
            float4 xv = *reinterpret_cast<const float4*>(&xs[k * 68 + r0]);
            const unsigned long long* wp =
                reinterpret_cast<const unsigned long long*>(&Wt[kl * 68 + c0]);
            unsigned long long w0 = wp[0];
            unsigned long long w1 = wp[1];
            unsigned long long x0 = dup_f32(xv.x);
            unsigned long long x1 = dup_f32(xv.y);
            unsigned long long x2 = dup_f32(xv.z);
            unsigned long long x3 = dup_f32(xv.w);
            fma2(acc2[0][0], x0, w0); fma2(acc2[0][1], x0, w1);
            fma2(acc2[1][0], x1, w0); fma2(acc2[1][1], x1, w1);
            fma2(acc2[2][0], x2, w0); fma2(acc2[2][1], x2, w1);
            fma2(acc2[3][0], x3, w0); fma2(acc2[3][1], x3, w1);
        }
    }

    #pragma unroll
    for (int i = 0; i < 4; ++i) {
        int row = row0 + r0 + i;
        if (row < N_NODES) {
            float2 a = unpack_f32x2(acc2[i][0]);
            float2 b = unpack_f32x2(acc2[i][1]);
            __half2 p0 = __floats2half2_rn(a.x, a.y);
            __half2 p1 = __floats2half2_rn(b.x, b.y);
            __half2* dst = reinterpret_cast<__half2*>(&d_g1[row * H_F + c0]);
            dst[0] = p0;
            dst[1] = p1;
        }
    }
}

// ---------------- gather L1: h = relu(dinv[i]*(Σ dinv[s]*g1[s]) + b1) -------
// One warp per dst node; 8-wide edge unroll + scalar remainder (R14 layout).
__global__ void gather1_kernel(const float* __restrict__ b1) {
    int warp = (blockIdx.x * blockDim.x + threadIdx.x) >> 5;
    int lane = threadIdx.x & 31;
    if (warp >= N_NODES) return;

    const __half2* g = reinterpret_cast<const __half2*>(d_g1);
    const int* __restrict__ ss = d_srcsorted;
    const float* __restrict__ dv = d_dinv;

    const float di = dv[warp];
    float2 sv = __half22float2(g[warp * 32 + lane]);
    float2 acc;                                      // self loop: dinv[i]*g1[i]
    acc.x = di * sv.x;
    acc.y = di * sv.y;
    int e = d_rowptr[warp];
    const int end = d_rowptr[warp + 1];

    for (; e + 8 <= end; e += 8) {
        int s0 = __ldg(&ss[e + 0]);
        int s1 = __ldg(&ss[e + 1]);
        int s2 = __ldg(&ss[e + 2]);
        int s3 = __ldg(&ss[e + 3]);
        int s4 = __ldg(&ss[e + 4]);
        int s5 = __ldg(&ss[e + 5]);
        int s6 = __ldg(&ss[e + 6]);
        int s7 = __ldg(&ss[e + 7]);
        float  e0 = __ldg(&dv[s0]);
        float  e1 = __ldg(&dv[s1]);
        float  e2 = __ldg(&dv[s2]);
        float  e3 = __ldg(&dv[s3]);
        float  e4 = __ldg(&dv[s4]);
        float  e5 = __ldg(&dv[s5]);
        float  e6 = __ldg(&dv[s6]);
        float  e7 = __ldg(&dv[s7]);
        float2 v0 = __half22float2(__ldg(&g[s0 * 32 + lane]));
        float2 v1 = __half22float2(__ldg(&g[s1 * 32 + lane]));
        float2 v2 = __half22float2(__ldg(&g[s2 * 32 + lane]));
        float2 v3 = __half22float2(__ldg(&g[s3 * 32 + lane]));
        float2 v4 = __half22float2(__ldg(&g[s4 * 32 + lane]));
        float2 v5 = __half22float2(__ldg(&g[s5 * 32 + lane]));
        float2 v6 = __half22float2(__ldg(&g[s6 * 32 + lane]));
        float2 v7 = __half22float2(__ldg(&g[s7 * 32 + lane]));
        float2 p, q;
        p.x = fmaf(e0, v0.x, fmaf(e1, v1.x, fmaf(e2, v2.x, e3 * v3.x)));
        p.y = fmaf(e0, v0.y, fmaf(e1, v1.y, fmaf(e2, v2.y, e3 * v3.y)));
        q.x = fmaf(e4, v4.x, fmaf(e5, v5.x, fmaf(e6, v6.x, e7 * v7.x)));
        q.y = fmaf(e4, v4.y, fmaf(e5, v5.y, fmaf(e6, v6.y, e7 * v7.y)));
        acc.x += p.x + q.x;
        acc.y += p.y + q.y;
    }
    for (; e < end; ++e) {
        int s = __ldg(&ss[e]);
        float ds = __ldg(&dv[s]);
        float2 v = __half22float2(__ldg(&g[s * 32 + lane]));
        acc.x = fmaf(ds, v.x, acc.x);
        acc.y = fmaf(ds, v.y, acc.y);
    }

    float2 b = __ldg(reinterpret_cast<const float2*>(b1) + lane);
    float2 h;
    h.x = fmaxf(fmaf(di, acc.x, b.x), 0.f);
    h.y = fmaxf(fmaf(di, acc.y, b.y), 0.f);
    reinterpret_cast<float2*>(d_h1)[warp * 32 + lane] = h;
}

// ---------------- GEMM2: g2[i,c] = fp16( dinv[i] * (h1[i,:] . W2[c,:]) ) -----
__global__ void gemm2_kernel(const float* __restrict__ W2) {
    __shared__ float ht[64 * 66];    // ht[j][r]
    __shared__ float Wt[64 * 36];    // Wt[j][c]
    const int tid = threadIdx.x;
    const int row0 = blockIdx.x * 64;

    for (int idx = tid; idx < 64 * 64; idx += 256) {
        int r = idx >> 6, j = idx & 63;
        int row = row0 + r;
        ht[j * 66 + r] = (row < N_NODES) ? d_h1[row * H_F + j] : 0.f;
    }
    for (int idx = tid; idx < 32 * 64; idx += 256) {
        int c = idx >> 6, j = idx & 63;
        Wt[j * 36 + c] = W2[c * H_F + j];
    }
    __syncthreads();

    const int r0 = (tid >> 3) * 2;
    const int c0 = (tid & 7) * 4;
    unsigned long long acc2[2][2] = {};

    #pragma unroll
    for (int j = 0; j < 64; ++j) {
        float2 hv = *reinterpret_cast<const float2*>(&ht[j * 66 + r0]);
        const unsigned long long* wp =
            reinterpret_cast<const unsigned long long*>(&Wt[j * 36 + c0]);
        unsigned long long w0 = wp[0];
        unsigned long long w1 = wp[1];
        unsigned long long h0 = dup_f32(hv.x);
        unsigned long long h1 = dup_f32(hv.y);
        fma2(acc2[0][0], h0, w0); fma2(acc2[0][1], h0, w1);
        fma2(acc2[1][0], h1, w0); fma2(acc2[1][1], h1, w1);
    }

    #pragma unroll
    for (int i = 0; i < 2; ++i) {
        int row = row0 + r0 + i;
        if (row < N_NODES) {
            float di = d_dinv[row];
            float2 a = unpack_f32x2(acc2[i][0]);
            float2 b = unpack_f32x2(acc2[i][1]);
            __half2 p0 = __floats2half2_rn(a.x * di, a.y * di);
            __half2 p1 = __floats2half2_rn(b.x * di, b.y * di);
            __half2* dst = reinterpret_cast<__half2*>(&d_g2[row * OUT_F + c0]);
            dst[0] = p0;
            dst[1] = p1;
        }
    }
}

// ---------------- gather L2 (CSR, fp16) + bias -> output (R14 layout) --------
__global__ void gather2_kernel(const float* __restrict__ b2,
                               float* __restrict__ out) {
    int warp = (blockIdx.x * blockDim.x + threadIdx.x) >> 5;
    int lane = threadIdx.x & 31;
    if (warp >= N_NODES) return;

    float acc = __half2float(d_g2[warp * OUT_F + lane]);   // self loop
    int e = d_rowptr[warp];
    const int end = d_rowptr[warp + 1];

    for (; e + 8 <= end; e += 8) {
        int s0 = __ldg(&d_srcsorted[e + 0]);
        int s1 = __ldg(&d_srcsorted[e + 1]);
        int s2 = __ldg(&d_srcsorted[e + 2]);
        int s3 = __ldg(&d_srcsorted[e + 3]);
        int s4 = __ldg(&d_srcsorted[e + 4]);
        int s5 = __ldg(&d_srcsorted[e + 5]);
        int s6 = __ldg(&d_srcsorted[e + 6]);
        int s7 = __ldg(&d_srcsorted[e + 7]);
        float v0 = __half2float(__ldg(&d_g2[s0 * OUT_F + lane]));
        float v1 = __half2float(__ldg(&d_g2[s1 * OUT_F + lane]));
        float v2 = __half2float(__ldg(&d_g2[s2 * OUT_F + lane]));
        float v3 = __half2float(__ldg(&d_g2[s3 * OUT_F + lane]));
        float v4 = __half2float(__ldg(&d_g2[s4 * OUT_F + lane]));
        float v5 = __half2float(__ldg(&d_g2[s5 * OUT_F + lane]));
        float v6 = __half2float(__ldg(&d_g2[s6 * OUT_F + lane]));
        float v7 = __half2float(__ldg(&d_g2[s7 * OUT_F + lane]));
        acc += ((v0 + v1) + (v2 + v3)) + ((v4 + v5) + (v6 + v7));
    }
    for (; e < end; ++e) {
        int s = __ldg(&d_srcsorted[e]);
        acc += __half2float(__ldg(&d_g2[s * OUT_F + lane]));
    }

    out[warp * OUT_F + lane] = fmaf(d_dinv[warp], acc, __ldg(&b2[lane]));
}

extern "C" void kernel_launch(void* const* d_in, const int* in_sizes, int n_in,
                              void* d_out, int out_size) {
    const float* x  = (const float*)d_in[0];
    const int*   ei = (const int*)  d_in[1];
    const float* W1 = (const float*)d_in[2];
    const float* b1 = (const float*)d_in[3];
    const float* W2 = (const float*)d_in[4];
    const float* b2 = (const float*)d_in[5];
    float* out = (float*)d_out;

    // Fork: CSR build on side stream; gemm1 (FMA-bound) on the main stream.
    cudaStream_t s;
    cudaStreamCreateWithFlags(&s, cudaStreamNonBlocking);
    cudaEvent_t ev_fork, ev_join;
    cudaEventCreateWithFlags(&ev_fork, cudaEventDisableTiming);
    cudaEventCreateWithFlags(&ev_join, cudaEventDisableTiming);

    cudaEventRecord(ev_fork, 0);
    cudaStreamWaitEvent(s, ev_fork, 0);

    // side stream: rank-splitting CSR build (fill is atomic-free)
    count_rank_kernel<<<(N_EDGES / 8 + 255) / 256, 256, 0, s>>>(ei);
    scan_a_kernel    <<<NB_SCAN, SCAN_BLK, 0, s>>>();
    scan_c_kernel    <<<(N_NODES + 255) / 256, 256, 0, s>>>();
    fill_kernel      <<<(N_EDGES / 4 + 255) / 256, 256, 0, s>>>(ei);
    cudaEventRecord(ev_join, s);

    // main stream: gemm1 (independent of CSR/dinv)
    gemm1_kernel <<<(N_NODES + 63) / 64, 256>>>(x, W1);

    // join, then the dependent tail
    cudaStreamWaitEvent(0, ev_join, 0);
    gather1_kernel<<<(N_NODES * 32 + 255) / 256, 256>>>(b1);
    gemm2_kernel  <<<(N_NODES + 63) / 64, 256>>>(W2);
    gather2_kernel<<<(N_NODES * 32 + 255) / 256, 256>>>(b2, out);
    // NOTE: stream/event handles intentionally not destroyed — destroying
    // capture-participating handles mid-capture is hazardous; kernel_launch
    // is invoked only a handful of times, so the leak is bounded, host-side.
}